// round 1
// baseline (speedup 1.0000x reference)
#include <cuda_runtime.h>
#include <cuda_bf16.h>
#include <cstdint>

// Problem constants: B=4096, H=1, E=8, IN=256, OUT=256
#define BATCH 4096
#define NEXP  8
#define NIN   256
#define NOUT  256
#define NPAT  256           // 2^E gate patterns
#define NW    8             // 256 bits / 32 = 8 words per i-dimension

// Sign-bit matrices for every gate pattern: Wbits[p][o][iw], bit l of word iw
// corresponds to input index i = iw*32 + l. 256*256*8*4B = 2 MB (L2-resident).
__device__ uint32_t g_Wbits[NPAT * NOUT * NW];

// ---------------------------------------------------------------------------
// Kernel 1: precompute sign bits of all 256 subset sums of the expert weights.
// One warp per (o, iw). Lane l owns i = iw*32 + l.
// Subset sums are built with a two-level DP that reproduces EXACT left-to-right
// ascending-e floating point summation (s = ((w_e1 + w_e2) + ...) + w_ek),
// which matches sum_e gate_e * W_e evaluated in e order.
// ---------------------------------------------------------------------------
__global__ void __launch_bounds__(256) precompute_wbits_kernel(
    const float* __restrict__ weight)   // [E, IN, OUT]
{
    const int gw   = (blockIdx.x * blockDim.x + threadIdx.x) >> 5;  // 0..2047
    const int lane = threadIdx.x & 31;
    const int o    = gw >> 3;        // 0..255
    const int iw   = gw & 7;         // 0..7
    const int i    = iw * 32 + lane; // 0..255

    float w[NEXP];
#pragma unroll
    for (int e = 0; e < NEXP; e++)
        w[e] = __ldg(&weight[(e * NIN + i) * NOUT + o]);

    // Low-nibble DP: sl[q] = LTR sum of w[e] for e in 0..3 selected by q.
    float sl[16];
    sl[0] = 0.0f;
#pragma unroll
    for (int e = 0; e < 4; e++) {
#pragma unroll
        for (int q = 0; q < 16; q++) {
            if (q < (1 << e)) sl[q | (1 << e)] = sl[q] + w[e];
        }
    }

    uint32_t keep[8];
#pragma unroll
    for (int g = 0; g < 8; g++) keep[g] = 0u;

#pragma unroll
    for (int pl = 0; pl < 16; pl++) {
        // High-nibble DP seeded with the low partial sum (preserves LTR order).
        float sh[16];
        sh[0] = sl[pl];
#pragma unroll
        for (int e = 0; e < 4; e++) {
#pragma unroll
            for (int q = 0; q < 16; q++) {
                if (q < (1 << e)) sh[q | (1 << e)] = sh[q] + w[4 + e];
            }
        }
#pragma unroll
        for (int ph = 0; ph < 16; ph++) {
            const int p = (ph << 4) | pl;                 // full pattern
            uint32_t bal = __ballot_sync(0xffffffffu, sh[ph] > 0.0f);
            if (lane == (p & 31)) keep[p >> 5] = bal;     // predicated keep
        }
    }

    // Each lane stores the 8 patterns with p%32 == lane.
#pragma unroll
    for (int g = 0; g < 8; g++) {
        const int p = g * 32 + lane;
        g_Wbits[(p * NOUT + o) * NW + iw] = keep[g];
    }
}

// ---------------------------------------------------------------------------
// Kernel 2: one warp per sample b.
//  1. gate logits z_e = x_b . proj_w_e + proj_b_e  -> pattern p (8 bits)
//  2. xbits = sign bits of x_b (8 words via ballot)
//  3. y[b,o] = (256 - 2*popc(xbits ^ Wbits[p][o])) * scale[o]
//  p == 0 means w == 0 -> sign(w) == 0 -> y == 0.
// ---------------------------------------------------------------------------
__global__ void __launch_bounds__(256) binlinear_kernel(
    const float* __restrict__ x,        // [B, IN]
    const float* __restrict__ proj_w,   // [E, IN]
    const float* __restrict__ proj_b,   // [E]
    const float* __restrict__ scale,    // [OUT]
    float* __restrict__ out)            // [B, OUT]
{
    const int b    = (blockIdx.x * blockDim.x + threadIdx.x) >> 5;  // 0..4095
    const int lane = threadIdx.x & 31;

    const float* xb = x + b * NIN;

    float xi[NW];
#pragma unroll
    for (int j = 0; j < NW; j++) xi[j] = __ldg(&xb[j * 32 + lane]);

    uint32_t xbits[NW];
#pragma unroll
    for (int j = 0; j < NW; j++)
        xbits[j] = __ballot_sync(0xffffffffu, xi[j] > 0.0f);

    // Gate pattern.
    unsigned p = 0u;
#pragma unroll
    for (int e = 0; e < NEXP; e++) {
        float s = 0.0f;
#pragma unroll
        for (int j = 0; j < NW; j++)
            s += xi[j] * __ldg(&proj_w[e * NIN + j * 32 + lane]);
#pragma unroll
        for (int d = 16; d > 0; d >>= 1)
            s += __shfl_xor_sync(0xffffffffu, s, d);
        if (s + __ldg(&proj_b[e]) > 0.0f) p |= (1u << e);
    }

    float* outb = out + b * NOUT;

    if (p == 0u) {   // warp-uniform
#pragma unroll
        for (int j = 0; j < NW; j++) outb[j * 32 + lane] = 0.0f;
        return;
    }

    const uint4* wrow = reinterpret_cast<const uint4*>(g_Wbits + p * (NOUT * NW));

#pragma unroll
    for (int j = 0; j < NW; j++) {
        const int o = j * 32 + lane;
        uint4 a = wrow[o * 2 + 0];
        uint4 c = wrow[o * 2 + 1];
        int acc = __popc(xbits[0] ^ a.x) + __popc(xbits[1] ^ a.y)
                + __popc(xbits[2] ^ a.z) + __popc(xbits[3] ^ a.w)
                + __popc(xbits[4] ^ c.x) + __popc(xbits[5] ^ c.y)
                + __popc(xbits[6] ^ c.z) + __popc(xbits[7] ^ c.w);
        outb[o] = (float)(NIN - 2 * acc) * __ldg(&scale[o]);
    }
}

// ---------------------------------------------------------------------------
// Launch. Inputs (metadata order): x, weight, proj_w, proj_b, scale.
// Identified defensively by element count (all distinct).
// ---------------------------------------------------------------------------
extern "C" void kernel_launch(void* const* d_in, const int* in_sizes, int n_in,
                              void* d_out, int out_size)
{
    const float* x      = nullptr;
    const float* weight = nullptr;
    const float* proj_w = nullptr;
    const float* proj_b = nullptr;
    const float* scale  = nullptr;

    for (int k = 0; k < n_in; k++) {
        switch (in_sizes[k]) {
            case BATCH * NIN:        x      = (const float*)d_in[k]; break; // 1048576
            case NEXP * NIN * NOUT:  weight = (const float*)d_in[k]; break; // 524288
            case NEXP * NIN:         proj_w = (const float*)d_in[k]; break; // 2048
            case NEXP:               proj_b = (const float*)d_in[k]; break; // 8
            case NOUT:               scale  = (const float*)d_in[k]; break; // 256
            default: break;
        }
    }

    float* out = (float*)d_out;

    // 2048 warps: 256 blocks x 256 threads.
    precompute_wbits_kernel<<<256, 256>>>(weight);
    // 4096 warps: 512 blocks x 256 threads.
    binlinear_kernel<<<512, 256>>>(x, proj_w, proj_b, scale, out);
}